// round 5
// baseline (speedup 1.0000x reference)
#include <cuda_runtime.h>
#include <cuda_bf16.h>
#include <math.h>
#include <stdint.h>

#define B_ 4
#define T_ 1024
#define F_ 128
#define D_ 512
#define H_ 8
#define L_ 4
#define DFF_ 2048
#define MD_ 20
#define HD_ 64
#define NT_ (B_*T_)
#define SCALE_ 0.125f
#define LOG2E_ 1.4426950408889634f
#define SC2_ (SCALE_*LOG2E_)

// ---------------- scratch (device globals: no allocations allowed) ----------
__device__ float g_x  [NT_*(size_t)D_];
__device__ float g_q  [NT_*(size_t)D_];
__device__ float g_k  [NT_*(size_t)D_];
__device__ float g_v  [NT_*(size_t)D_];
__device__ float g_o  [NT_*(size_t)D_];
__device__ float g_ffn[NT_*(size_t)DFF_];
__device__ __nv_bfloat16 g_biash[(size_t)B_*H_*T_*T_];   // bias * log2(e), bf16

// ---------------- tf32 helpers ----------------------------------------------
__device__ __forceinline__ float to_tf32(float x) {
    float y; asm("cvt.rna.tf32.f32 %0, %1;" : "=f"(y) : "f"(x)); return y;
}
__device__ __forceinline__ float4 cvt4(float4 v) {
    v.x = to_tf32(v.x); v.y = to_tf32(v.y); v.z = to_tf32(v.z); v.w = to_tf32(v.w);
    return v;
}
__device__ __forceinline__ float ex2(float x) {
    float y; asm("ex2.approx.f32 %0, %1;" : "=f"(y) : "f"(x)); return y;
}
// D += A(16x8,row) * B(8x8,col);  A,B hold tf32 bit patterns in fp32 regs.
__device__ __forceinline__ void mma8(float* d, const float* a, const float* b) {
    asm volatile(
      "mma.sync.aligned.m16n8k8.row.col.f32.tf32.tf32.f32 "
      "{%0,%1,%2,%3}, {%4,%5,%6,%7}, {%8,%9}, {%0,%1,%2,%3};\n"
      : "+f"(d[0]), "+f"(d[1]), "+f"(d[2]), "+f"(d[3])
      : "r"(__float_as_uint(a[0])), "r"(__float_as_uint(a[1])),
        "r"(__float_as_uint(a[2])), "r"(__float_as_uint(a[3])),
        "r"(__float_as_uint(b[0])), "r"(__float_as_uint(b[1])));
}

__device__ __forceinline__ float warp_red_sum(float v) {
    #pragma unroll
    for (int o = 16; o > 0; o >>= 1) v += __shfl_xor_sync(0xffffffffu, v, o);
    return v;
}

// ---------------- tf32 GEMM: C[M=4096, N] = act(A[M,K] @ W[K,N] + bias) -----
// 128x128x32 block tile, 256 threads, warp tile 64x32 (m16n8k8 frags).
struct GemmP {
    const float* A;
    const float* W[3];
    const float* bias[3];
    float*       C[3];
    const float* resid;
    int K, N;
};

template<int ACT, bool RESID>
__global__ __launch_bounds__(256)
void gemm_tf32(GemmP p)
{
    __shared__ float As[128*36];
    __shared__ float Bs[32*136];

    const int z = blockIdx.z;
    const float* __restrict__ A    = p.A;
    const float* __restrict__ W    = p.W[z];
    const float* __restrict__ bias = p.bias[z];
    float*       __restrict__ C    = p.C[z];
    const float* __restrict__ resid = p.resid;
    const int K = p.K, N = p.N;
    const int m0 = blockIdx.y * 128, n0 = blockIdx.x * 128;

    const int tid  = threadIdx.x;
    const int warp = tid >> 5, lane = tid & 31;
    const int g  = lane >> 2, qd = lane & 3;
    const int wm = (warp >> 2) * 64;
    const int wn = (warp & 3)  * 32;

    const int a_m  = tid >> 3;
    const int a_k4 = tid & 7;
    const int b_k  = tid >> 5;
    const int b_n4 = tid & 31;

    float4 ra[4], rb[4];
    float acc[4][4][4];
    #pragma unroll
    for (int i = 0; i < 4; i++)
        #pragma unroll
        for (int j = 0; j < 4; j++)
            #pragma unroll
            for (int u = 0; u < 4; u++) acc[i][j][u] = 0.f;

    #pragma unroll
    for (int i = 0; i < 4; i++)
        ra[i] = *(const float4*)&A[(size_t)(m0 + a_m + 32*i) * K + a_k4*4];
    #pragma unroll
    for (int i = 0; i < 4; i++)
        rb[i] = *(const float4*)&W[(size_t)(b_k + 8*i) * N + n0 + b_n4*4];

    const int nk = K >> 5;
    for (int kt = 0; kt < nk; kt++) {
        #pragma unroll
        for (int i = 0; i < 4; i++) {
            const int m = a_m + 32*i;
            *(float4*)&As[m*36 + ((a_k4*4) ^ ((m & 3) << 3))] = cvt4(ra[i]);
        }
        #pragma unroll
        for (int i = 0; i < 4; i++)
            *(float4*)&Bs[(b_k + 8*i)*136 + b_n4*4] = cvt4(rb[i]);
        __syncthreads();

        if (kt + 1 < nk) {
            const int k0 = (kt + 1) << 5;
            #pragma unroll
            for (int i = 0; i < 4; i++)
                ra[i] = *(const float4*)&A[(size_t)(m0 + a_m + 32*i) * K + k0 + a_k4*4];
            #pragma unroll
            for (int i = 0; i < 4; i++)
                rb[i] = *(const float4*)&W[(size_t)(k0 + b_k + 8*i) * N + n0 + b_n4*4];
        }

        #pragma unroll
        for (int kk = 0; kk < 4; kk++) {
            const int kb = kk * 8;
            float afr[4][4], bfr[4][2];
            #pragma unroll
            for (int mi = 0; mi < 4; mi++) {
                const int m_ = wm + mi*16 + g;
                const int sw = (m_ & 3) << 3;
                afr[mi][0] = As[ m_     *36 + ((kb + qd    ) ^ sw)];
                afr[mi][1] = As[(m_ + 8)*36 + ((kb + qd    ) ^ sw)];
                afr[mi][2] = As[ m_     *36 + ((kb + qd + 4) ^ sw)];
                afr[mi][3] = As[(m_ + 8)*36 + ((kb + qd + 4) ^ sw)];
            }
            #pragma unroll
            for (int ni = 0; ni < 4; ni++) {
                const int n_ = wn + ni*8 + g;
                bfr[ni][0] = Bs[(kb + qd    )*136 + n_];
                bfr[ni][1] = Bs[(kb + qd + 4)*136 + n_];
            }
            #pragma unroll
            for (int mi = 0; mi < 4; mi++)
                #pragma unroll
                for (int ni = 0; ni < 4; ni++)
                    mma8(acc[mi][ni], afr[mi], bfr[ni]);
        }
        __syncthreads();
    }

    #pragma unroll
    for (int mi = 0; mi < 4; mi++) {
        const int r0 = m0 + wm + mi*16 + g;
        #pragma unroll
        for (int ni = 0; ni < 4; ni++) {
            const int c0 = n0 + wn + ni*8 + qd*2;
            const float2 bv = *(const float2*)&bias[c0];
            float v0 = acc[mi][ni][0] + bv.x;
            float v1 = acc[mi][ni][1] + bv.y;
            float v2 = acc[mi][ni][2] + bv.x;
            float v3 = acc[mi][ni][3] + bv.y;
            if (ACT == 1) {
                v0 = v0 / (1.0f + __expf(-v0));
                v1 = v1 / (1.0f + __expf(-v1));
                v2 = v2 / (1.0f + __expf(-v2));
                v3 = v3 / (1.0f + __expf(-v3));
            }
            if (RESID) {
                const float2 r1 = *(const float2*)&resid[(size_t)r0 * N + c0];
                const float2 r2 = *(const float2*)&resid[(size_t)(r0 + 8) * N + c0];
                v0 += r1.x; v1 += r1.y; v2 += r2.x; v3 += r2.y;
            }
            *(float2*)&C[(size_t)r0       * N + c0] = make_float2(v0, v1);
            *(float2*)&C[(size_t)(r0 + 8) * N + c0] = make_float2(v2, v3);
        }
    }
}

// ---------------- fused flash attention (tf32) ------------------------------
// Grid (T/128, B*H), 256 threads = 8 warps; each warp owns 16 q-rows x full
// 64-col j tile -> online softmax fully warp-local (quad shuffles only).
// S/P/O all stay on-chip; bias read as bf16 (pre-scaled by log2e).
#define FL_SMEM (123904)

__global__ __launch_bounds__(256, 1)
void flash_tf32(const float* __restrict__ q, const float* __restrict__ k,
                const float* __restrict__ v,
                const __nv_bfloat16* __restrict__ biash,
                float* __restrict__ o)
{
    extern __shared__ char smem_raw[];
    float* Qs = (float*)smem_raw;                 // [128][68] swizzled
    float* Ks = Qs + 128*68;                      // [64][68]
    float* Vs = Ks + 64*68;                       // [64][72]
    float* Ps = Vs + 64*72;                       // [128][68] swizzled
    __nv_bfloat16* Bs = (__nv_bfloat16*)(Ps + 128*68);   // [128][72]

    const int z = blockIdx.y;
    const int b = z >> 3, h = z & 7;
    const int i0 = blockIdx.x * 128;
    const float* qp = q + (size_t)b*T_*D_ + h*HD_;
    const float* kp = k + (size_t)b*T_*D_ + h*HD_;
    const float* vp = v + (size_t)b*T_*D_ + h*HD_;
    const __nv_bfloat16* bp = biash + (size_t)z*T_*T_;

    const int tid = threadIdx.x;
    const int warp = tid >> 5, lane = tid & 31;
    const int g = lane >> 2, qd = lane & 3;
    const int slab = warp * 16;
    const int sw = (g & 3) << 3;          // (row&3)<<3 for rows slab+g, slab+g+8

    // load Q tile (tf32)
    #pragma unroll
    for (int u = 0; u < 8; u++) {
        const int idx = u*256 + tid;
        const int r = idx >> 4, d4 = idx & 15;
        float4 val = cvt4(*(const float4*)&qp[(size_t)(i0 + r)*D_ + d4*4]);
        *(float4*)&Qs[r*68 + ((d4*4) ^ ((r & 3) << 3))] = val;
    }

    float m0 = -1e30f, m1 = -1e30f, l0 = 0.f, l1 = 0.f;
    float oacc[8][4];
    #pragma unroll
    for (int n = 0; n < 8; n++)
        #pragma unroll
        for (int u = 0; u < 4; u++) oacc[n][u] = 0.f;

    for (int jt = 0; jt < T_/64; jt++) {
        const int j0 = jt * 64;
        __syncthreads();   // prev iter's O-mma done with Vs; safe to overwrite
        #pragma unroll
        for (int u = 0; u < 4; u++) {
            const int idx = u*256 + tid;
            const int r = idx >> 4, d4 = idx & 15;
            *(float4*)&Ks[r*68 + d4*4] = cvt4(*(const float4*)&kp[(size_t)(j0 + r)*D_ + d4*4]);
            *(float4*)&Vs[r*72 + d4*4] = cvt4(*(const float4*)&vp[(size_t)(j0 + r)*D_ + d4*4]);
            const int br = idx >> 3, seg = idx & 7;
            *(uint4*)&Bs[br*72 + seg*8] =
                *(const uint4*)&bp[(size_t)(i0 + br)*T_ + j0 + seg*8];
        }
        __syncthreads();

        // S = Q K^T
        float sacc[8][4];
        #pragma unroll
        for (int n = 0; n < 8; n++)
            #pragma unroll
            for (int u = 0; u < 4; u++) sacc[n][u] = 0.f;
        #pragma unroll
        for (int kk = 0; kk < 8; kk++) {
            const int kb = kk * 8;
            const int mr = slab + g;
            float afr[4];
            afr[0] = Qs[ mr     *68 + ((kb + qd    ) ^ sw)];
            afr[1] = Qs[(mr + 8)*68 + ((kb + qd    ) ^ sw)];
            afr[2] = Qs[ mr     *68 + ((kb + qd + 4) ^ sw)];
            afr[3] = Qs[(mr + 8)*68 + ((kb + qd + 4) ^ sw)];
            #pragma unroll
            for (int n = 0; n < 8; n++) {
                const int nr = n*8 + g;
                float bfr[2];
                bfr[0] = Ks[nr*68 + kb + qd];
                bfr[1] = Ks[nr*68 + kb + qd + 4];
                mma8(sacc[n], afr, bfr);
            }
        }

        // epilogue: s2 = sacc*SC2 + bias2 (log2 domain), online softmax
        float sv[8][4];
        float mx0 = -1e30f, mx1 = -1e30f;
        #pragma unroll
        for (int n = 0; n < 8; n++) {
            const int c = n*8 + qd*2;
            const float2 bv0 = __bfloat1622float2(*(const __nv_bfloat162*)&Bs[(slab+g  )*72 + c]);
            const float2 bv1 = __bfloat1622float2(*(const __nv_bfloat162*)&Bs[(slab+g+8)*72 + c]);
            sv[n][0] = fmaf(sacc[n][0], SC2_, bv0.x);
            sv[n][1] = fmaf(sacc[n][1], SC2_, bv0.y);
            sv[n][2] = fmaf(sacc[n][2], SC2_, bv1.x);
            sv[n][3] = fmaf(sacc[n][3], SC2_, bv1.y);
            mx0 = fmaxf(mx0, fmaxf(sv[n][0], sv[n][1]));
            mx1 = fmaxf(mx1, fmaxf(sv[n][2], sv[n][3]));
        }
        mx0 = fmaxf(mx0, __shfl_xor_sync(0xffffffffu, mx0, 1));
        mx0 = fmaxf(mx0, __shfl_xor_sync(0xffffffffu, mx0, 2));
        mx1 = fmaxf(mx1, __shfl_xor_sync(0xffffffffu, mx1, 1));
        mx1 = fmaxf(mx1, __shfl_xor_sync(0xffffffffu, mx1, 2));

        const float mn0 = fmaxf(m0, mx0), mn1 = fmaxf(m1, mx1);
        const float al0 = ex2(m0 - mn0),  al1 = ex2(m1 - mn1);
        float rs0 = 0.f, rs1 = 0.f;
        #pragma unroll
        for (int n = 0; n < 8; n++) {
            const float p0 = ex2(sv[n][0] - mn0);
            const float p1 = ex2(sv[n][1] - mn0);
            const float p2 = ex2(sv[n][2] - mn1);
            const float p3 = ex2(sv[n][3] - mn1);
            rs0 += p0 + p1; rs1 += p2 + p3;
            const int c = (n*8 + qd*2) ^ sw;
            *(float2*)&Ps[(slab+g  )*68 + c] = make_float2(to_tf32(p0), to_tf32(p1));
            *(float2*)&Ps[(slab+g+8)*68 + c] = make_float2(to_tf32(p2), to_tf32(p3));
            oacc[n][0] *= al0; oacc[n][1] *= al0;
            oacc[n][2] *= al1; oacc[n][3] *= al1;
        }
        rs0 += __shfl_xor_sync(0xffffffffu, rs0, 1);
        rs0 += __shfl_xor_sync(0xffffffffu, rs0, 2);
        rs1 += __shfl_xor_sync(0xffffffffu, rs1, 1);
        rs1 += __shfl_xor_sync(0xffffffffu, rs1, 2);
        l0 = l0*al0 + rs0;  m0 = mn0;
        l1 = l1*al1 + rs1;  m1 = mn1;

        __syncwarp();   // P rows are warp-private; only intra-warp visibility needed

        // O += P @ V
        #pragma unroll
        for (int kk = 0; kk < 8; kk++) {
            const int kb = kk * 8;
            const int mr = slab + g;
            float afr[4];
            afr[0] = Ps[ mr     *68 + ((kb + qd    ) ^ sw)];
            afr[1] = Ps[(mr + 8)*68 + ((kb + qd    ) ^ sw)];
            afr[2] = Ps[ mr     *68 + ((kb + qd + 4) ^ sw)];
            afr[3] = Ps[(mr + 8)*68 + ((kb + qd + 4) ^ sw)];
            #pragma unroll
            for (int n = 0; n < 8; n++) {
                float bfr[2];
                bfr[0] = Vs[(kb + qd    )*72 + n*8 + g];
                bfr[1] = Vs[(kb + qd + 4)*72 + n*8 + g];
                mma8(oacc[n], afr, bfr);
            }
        }
    }

    const float inv0 = 1.0f / l0, inv1 = 1.0f / l1;
    const size_t r0 = (size_t)b*T_ + i0 + slab + g;
    #pragma unroll
    for (int n = 0; n < 8; n++) {
        const int c = h*HD_ + n*8 + qd*2;
        *(float2*)&o[ r0      * D_ + c] = make_float2(oacc[n][0]*inv0, oacc[n][1]*inv0);
        *(float2*)&o[(r0 + 8) * D_ + c] = make_float2(oacc[n][2]*inv1, oacc[n][3]*inv1);
    }
}

// ---------------- embedding extras ------------------------------------------
__global__ void add_cent_kernel(float* __restrict__ h, const float* __restrict__ cent,
                                const float* __restrict__ cw, const float* __restrict__ cb)
{
    const int n = blockIdx.x, d = threadIdx.x;
    h[(size_t)n * D_ + d] += cent[n] * cw[d] + cb[d];
}

// biash[b,h,i,j] = (edge_emb[et,h] + dist_emb[sp,h]) * log2(e)  as bf16
__global__ void bias_kernel(const int* __restrict__ et, const int* __restrict__ sp,
                            const float* __restrict__ ee, const float* __restrict__ de,
                            __nv_bfloat16* __restrict__ bias)
{
    const size_t tid = (size_t)blockIdx.x * blockDim.x + threadIdx.x;  // B*T*T
    const int e = et[tid];
    int s = sp[tid]; if (s > MD_) s = MD_; if (s < 0) s = 0;
    const size_t j = tid & (T_ - 1);
    const size_t i = (tid >> 10) & (T_ - 1);
    const size_t b = tid >> 20;
    #pragma unroll
    for (int hh = 0; hh < H_; hh++)
        bias[(((b*H_ + hh)*T_ + i)*T_) + j] =
            __float2bfloat16((ee[e*H_ + hh] + de[s*H_ + hh]) * LOG2E_);
}

// ---------------- layernorm --------------------------------------------------
__global__ __launch_bounds__(128)
void ln_kernel(const float* __restrict__ h, const float* __restrict__ w,
               const float* __restrict__ b, float* __restrict__ out)
{
    __shared__ float red[8];
    const int t = threadIdx.x;
    const float* hp = h + (size_t)blockIdx.x * D_;
    float v[4]; float s = 0.f, s2 = 0.f;
    #pragma unroll
    for (int u = 0; u < 4; u++) { v[u] = hp[t + u*128]; s += v[u]; s2 += v[u]*v[u]; }
    s  = warp_red_sum(s);
    s2 = warp_red_sum(s2);
    if ((t & 31) == 0) { red[t>>5] = s; red[4 + (t>>5)] = s2; }
    __syncthreads();
    s  = red[0] + red[1] + red[2] + red[3];
    s2 = red[4] + red[5] + red[6] + red[7];
    const float m   = s  * (1.0f / D_);
    const float var = s2 * (1.0f / D_) - m * m;
    const float r   = rsqrtf(var + 1e-5f);
    float* op = out + (size_t)blockIdx.x * D_;
    #pragma unroll
    for (int u = 0; u < 4; u++) {
        const int d = t + u*128;
        op[d] = (v[u] - m) * r * w[d] + b[d];
    }
}

// ---------------- host-side orchestration -----------------------------------
static inline void gemm1(const float* A, const float* W, const float* bias,
                         const float* resid, float* C, int K, int N, int act)
{
    GemmP p;
    p.A = A;
    p.W[0] = p.W[1] = p.W[2] = W;
    p.bias[0] = p.bias[1] = p.bias[2] = bias;
    p.C[0] = p.C[1] = p.C[2] = C;
    p.resid = resid;
    p.K = K; p.N = N;
    dim3 g(N / 128, NT_ / 128, 1);
    if (act == 1)        gemm_tf32<1,false><<<g,256>>>(p);
    else if (resid)      gemm_tf32<0,true ><<<g,256>>>(p);
    else                 gemm_tf32<0,false><<<g,256>>>(p);
}

extern "C" void kernel_launch(void* const* d_in, const int* in_sizes, int n_in,
                              void* d_out, int out_size)
{
    const float* nf     = (const float*)d_in[0];
    const float* cent   = (const float*)d_in[1];
    const int*   et     = (const int*)  d_in[2];
    const int*   sp     = (const int*)  d_in[3];
    const float* node_W = (const float*)d_in[4];
    const float* node_b = (const float*)d_in[5];
    const float* cent_W = (const float*)d_in[6];
    const float* cent_b = (const float*)d_in[7];
    const float* e_emb  = (const float*)d_in[8];
    const float* d_emb  = (const float*)d_in[9];
    const float* ln1w   = (const float*)d_in[10];
    const float* ln1b   = (const float*)d_in[11];
    const float* qW     = (const float*)d_in[12];
    const float* qb     = (const float*)d_in[13];
    const float* kW     = (const float*)d_in[14];
    const float* kb     = (const float*)d_in[15];
    const float* vW     = (const float*)d_in[16];
    const float* vb     = (const float*)d_in[17];
    const float* oW     = (const float*)d_in[18];
    const float* ob     = (const float*)d_in[19];
    const float* ln2w   = (const float*)d_in[20];
    const float* ln2b   = (const float*)d_in[21];
    const float* f1W    = (const float*)d_in[22];
    const float* f1b    = (const float*)d_in[23];
    const float* f2W    = (const float*)d_in[24];
    const float* f2b    = (const float*)d_in[25];

    float* h = (float*)d_out;

    float *px, *pq, *pk, *pv, *po, *pffn;
    __nv_bfloat16* pbias;
    cudaGetSymbolAddress((void**)&px,    g_x);
    cudaGetSymbolAddress((void**)&pq,    g_q);
    cudaGetSymbolAddress((void**)&pk,    g_k);
    cudaGetSymbolAddress((void**)&pv,    g_v);
    cudaGetSymbolAddress((void**)&po,    g_o);
    cudaGetSymbolAddress((void**)&pffn,  g_ffn);
    cudaGetSymbolAddress((void**)&pbias, g_biash);

    cudaFuncSetAttribute(flash_tf32, cudaFuncAttributeMaxDynamicSharedMemorySize, FL_SMEM);

    // embedding: h = nf @ node_W + node_b ; h += cent*cent_W + cent_b
    gemm1(nf, node_W, node_b, nullptr, h, F_, D_, 0);
    add_cent_kernel<<<NT_, D_>>>(h, cent, cent_W, cent_b);

    // Graphormer attention bias (layer-invariant), bf16, log2e pre-folded
    bias_kernel<<<(B_*T_*T_)/256, 256>>>(et, sp, e_emb, d_emb, pbias);

    for (int l = 0; l < L_; l++) {
        const size_t wd = (size_t)l * D_ * D_;
        // x = LN1(h)
        ln_kernel<<<NT_, 128>>>(h, ln1w + l*D_, ln1b + l*D_, px);
        // q,k,v in one batched launch (grid.z = 3)
        {
            GemmP p;
            p.A = px;
            p.W[0] = qW + wd;  p.W[1] = kW + wd;  p.W[2] = vW + wd;
            p.bias[0] = qb + l*D_; p.bias[1] = kb + l*D_; p.bias[2] = vb + l*D_;
            p.C[0] = pq; p.C[1] = pk; p.C[2] = pv;
            p.resid = nullptr;
            p.K = D_; p.N = D_;
            gemm_tf32<0,false><<<dim3(D_/128, NT_/128, 3), 256>>>(p);
        }
        // fused attention: scores + softmax + AV, no global scores
        flash_tf32<<<dim3(T_/128, B_*H_), 256, FL_SMEM>>>(pq, pk, pv, pbias, po);
        // h += o @ oW + ob
        gemm1(po, oW + wd, ob + l*D_, h, h, D_, D_, 0);
        // FFN
        ln_kernel<<<NT_, 128>>>(h, ln2w + l*D_, ln2b + l*D_, px);
        gemm1(px,   f1W + (size_t)l*D_*DFF_, f1b + l*DFF_, nullptr, pffn, D_,   DFF_, 1);
        gemm1(pffn, f2W + (size_t)l*DFF_*D_, f2b + l*D_,   h,       h,    DFF_, D_,   0);
    }
}

// round 6
// speedup vs baseline: 1.4783x; 1.4783x over previous
#include <cuda_runtime.h>
#include <cuda_bf16.h>
#include <math.h>
#include <stdint.h>

#define B_ 4
#define T_ 1024
#define F_ 128
#define D_ 512
#define H_ 8
#define L_ 4
#define DFF_ 2048
#define MD_ 20
#define HD_ 64
#define NT_ (B_*T_)
#define SCALE_ 0.125f
#define LOG2E_ 1.4426950408889634f
#define SC2_ (SCALE_*LOG2E_)

// ---------------- scratch (device globals: no allocations allowed) ----------
__device__ float g_x  [NT_*(size_t)D_];
__device__ float g_q  [NT_*(size_t)D_];
__device__ float g_k  [NT_*(size_t)D_];
__device__ float g_v  [NT_*(size_t)D_];
__device__ float g_o  [NT_*(size_t)D_];
__device__ float g_ffn[NT_*(size_t)DFF_];
__device__ __nv_bfloat16 g_biash[(size_t)B_*H_*T_*T_];   // bias * log2(e), bf16

// ---------------- tf32 helpers ----------------------------------------------
__device__ __forceinline__ float to_tf32(float x) {
    float y; asm("cvt.rna.tf32.f32 %0, %1;" : "=f"(y) : "f"(x)); return y;
}
__device__ __forceinline__ float4 cvt4(float4 v) {
    v.x = to_tf32(v.x); v.y = to_tf32(v.y); v.z = to_tf32(v.z); v.w = to_tf32(v.w);
    return v;
}
__device__ __forceinline__ float ex2(float x) {
    float y; asm("ex2.approx.f32 %0, %1;" : "=f"(y) : "f"(x)); return y;
}
// D += A(16x8,row) * B(8x8,col);  A,B hold tf32 bit patterns in fp32 regs.
__device__ __forceinline__ void mma8(float* d, const float* a, const float* b) {
    asm volatile(
      "mma.sync.aligned.m16n8k8.row.col.f32.tf32.tf32.f32 "
      "{%0,%1,%2,%3}, {%4,%5,%6,%7}, {%8,%9}, {%0,%1,%2,%3};\n"
      : "+f"(d[0]), "+f"(d[1]), "+f"(d[2]), "+f"(d[3])
      : "r"(__float_as_uint(a[0])), "r"(__float_as_uint(a[1])),
        "r"(__float_as_uint(a[2])), "r"(__float_as_uint(a[3])),
        "r"(__float_as_uint(b[0])), "r"(__float_as_uint(b[1])));
}

__device__ __forceinline__ float warp_red_sum(float v) {
    #pragma unroll
    for (int o = 16; o > 0; o >>= 1) v += __shfl_xor_sync(0xffffffffu, v, o);
    return v;
}

// ---------------- tf32 GEMM: C[M=4096, N] = act(A[M,K] @ W[K,N] + bias) -----
// 128x128x32 block tile, 256 threads, warp tile 64x32 (m16n8k8 frags).
struct GemmP {
    const float* A;
    const float* W[3];
    const float* bias[3];
    float*       C[3];
    const float* resid;
    int K, N;
};

template<int ACT, bool RESID>
__global__ __launch_bounds__(256)
void gemm_tf32(GemmP p)
{
    __shared__ float As[128*36];
    __shared__ float Bs[32*136];

    const int z = blockIdx.z;
    const float* __restrict__ A    = p.A;
    const float* __restrict__ W    = p.W[z];
    const float* __restrict__ bias = p.bias[z];
    float*       __restrict__ C    = p.C[z];
    const float* __restrict__ resid = p.resid;
    const int K = p.K, N = p.N;
    const int m0 = blockIdx.y * 128, n0 = blockIdx.x * 128;

    const int tid  = threadIdx.x;
    const int warp = tid >> 5, lane = tid & 31;
    const int g  = lane >> 2, qd = lane & 3;
    const int wm = (warp >> 2) * 64;
    const int wn = (warp & 3)  * 32;

    const int a_m  = tid >> 3;
    const int a_k4 = tid & 7;
    const int b_k  = tid >> 5;
    const int b_n4 = tid & 31;

    float4 ra[4], rb[4];
    float acc[4][4][4];
    #pragma unroll
    for (int i = 0; i < 4; i++)
        #pragma unroll
        for (int j = 0; j < 4; j++)
            #pragma unroll
            for (int u = 0; u < 4; u++) acc[i][j][u] = 0.f;

    #pragma unroll
    for (int i = 0; i < 4; i++)
        ra[i] = *(const float4*)&A[(size_t)(m0 + a_m + 32*i) * K + a_k4*4];
    #pragma unroll
    for (int i = 0; i < 4; i++)
        rb[i] = *(const float4*)&W[(size_t)(b_k + 8*i) * N + n0 + b_n4*4];

    const int nk = K >> 5;
    for (int kt = 0; kt < nk; kt++) {
        #pragma unroll
        for (int i = 0; i < 4; i++) {
            const int m = a_m + 32*i;
            *(float4*)&As[m*36 + ((a_k4*4) ^ ((m & 3) << 3))] = cvt4(ra[i]);
        }
        #pragma unroll
        for (int i = 0; i < 4; i++)
            *(float4*)&Bs[(b_k + 8*i)*136 + b_n4*4] = cvt4(rb[i]);
        __syncthreads();

        if (kt + 1 < nk) {
            const int k0 = (kt + 1) << 5;
            #pragma unroll
            for (int i = 0; i < 4; i++)
                ra[i] = *(const float4*)&A[(size_t)(m0 + a_m + 32*i) * K + k0 + a_k4*4];
            #pragma unroll
            for (int i = 0; i < 4; i++)
                rb[i] = *(const float4*)&W[(size_t)(k0 + b_k + 8*i) * N + n0 + b_n4*4];
        }

        #pragma unroll
        for (int kk = 0; kk < 4; kk++) {
            const int kb = kk * 8;
            float afr[4][4], bfr[4][2];
            #pragma unroll
            for (int mi = 0; mi < 4; mi++) {
                const int m_ = wm + mi*16 + g;
                const int sw = (m_ & 3) << 3;
                afr[mi][0] = As[ m_     *36 + ((kb + qd    ) ^ sw)];
                afr[mi][1] = As[(m_ + 8)*36 + ((kb + qd    ) ^ sw)];
                afr[mi][2] = As[ m_     *36 + ((kb + qd + 4) ^ sw)];
                afr[mi][3] = As[(m_ + 8)*36 + ((kb + qd + 4) ^ sw)];
            }
            #pragma unroll
            for (int ni = 0; ni < 4; ni++) {
                const int n_ = wn + ni*8 + g;
                bfr[ni][0] = Bs[(kb + qd    )*136 + n_];
                bfr[ni][1] = Bs[(kb + qd + 4)*136 + n_];
            }
            #pragma unroll
            for (int mi = 0; mi < 4; mi++)
                #pragma unroll
                for (int ni = 0; ni < 4; ni++)
                    mma8(acc[mi][ni], afr[mi], bfr[ni]);
        }
        __syncthreads();
    }

    #pragma unroll
    for (int mi = 0; mi < 4; mi++) {
        const int r0 = m0 + wm + mi*16 + g;
        #pragma unroll
        for (int ni = 0; ni < 4; ni++) {
            const int c0 = n0 + wn + ni*8 + qd*2;
            const float2 bv = *(const float2*)&bias[c0];
            float v0 = acc[mi][ni][0] + bv.x;
            float v1 = acc[mi][ni][1] + bv.y;
            float v2 = acc[mi][ni][2] + bv.x;
            float v3 = acc[mi][ni][3] + bv.y;
            if (ACT == 1) {
                v0 = v0 / (1.0f + __expf(-v0));
                v1 = v1 / (1.0f + __expf(-v1));
                v2 = v2 / (1.0f + __expf(-v2));
                v3 = v3 / (1.0f + __expf(-v3));
            }
            if (RESID) {
                const float2 r1 = *(const float2*)&resid[(size_t)r0 * N + c0];
                const float2 r2 = *(const float2*)&resid[(size_t)(r0 + 8) * N + c0];
                v0 += r1.x; v1 += r1.y; v2 += r2.x; v3 += r2.y;
            }
            *(float2*)&C[(size_t)r0       * N + c0] = make_float2(v0, v1);
            *(float2*)&C[(size_t)(r0 + 8) * N + c0] = make_float2(v2, v3);
        }
    }
}

// ---------------- fused flash attention (tf32), high-occupancy re-tile ------
// Grid (T/64, B*H), 128 threads = 4 warps; warp owns 16 q-rows x full 64-col
// j tile -> warp-local online softmax (quad shuffles only).
// smem 69KB -> 3 CTAs/SM. Bias staged bf16 INSIDE the P buffer, per-warp
// interleaved so each warp's bias rows live in its own P slab (no cross-warp
// hazard; __syncwarp between bias-frag reads and P writes).
#define FL_SMEM (70656)

__global__ __launch_bounds__(128, 3)
void flash_tf32(const float* __restrict__ q, const float* __restrict__ k,
                const float* __restrict__ v,
                const __nv_bfloat16* __restrict__ biash,
                float* __restrict__ o)
{
    extern __shared__ char smem_raw[];
    float* Qs = (float*)smem_raw;                 // [64][68] swizzled
    float* Ks = Qs + 64*68;                       // [64][68]
    float* Vs = Ks + 64*68;                       // [64][72]
    float* Ps = Vs + 64*72;                       // [64][68] swizzled (union w/ bias)
    __nv_bfloat16* Bb = (__nv_bfloat16*)Ps;       // bias: warp w rows at w*2176 + (r&15)*72

    const int z = blockIdx.y;
    const int b = z >> 3, h = z & 7;
    const int i0 = blockIdx.x * 64;
    const float* qp = q + (size_t)b*T_*D_ + h*HD_;
    const float* kp = k + (size_t)b*T_*D_ + h*HD_;
    const float* vp = v + (size_t)b*T_*D_ + h*HD_;
    const __nv_bfloat16* bp = biash + (size_t)z*T_*T_;

    const int tid = threadIdx.x;
    const int warp = tid >> 5, lane = tid & 31;
    const int g = lane >> 2, qd = lane & 3;
    const int slab = warp * 16;
    const int sw = (g & 3) << 3;          // swizzle for rows slab+g, slab+g+8
    float* Pw = Ps + warp * 1088;         // this warp's P slab [16][68]

    // load Q tile (tf32): 64 rows x 16 float4 = 1024, 128 threads -> 8 iters
    #pragma unroll
    for (int u = 0; u < 8; u++) {
        const int idx = u*128 + tid;
        const int r = idx >> 4, d4 = idx & 15;
        float4 val = cvt4(*(const float4*)&qp[(size_t)(i0 + r)*D_ + d4*4]);
        *(float4*)&Qs[r*68 + ((d4*4) ^ ((r & 3) << 3))] = val;
    }

    float m0 = -1e30f, m1 = -1e30f, l0 = 0.f, l1 = 0.f;
    float oacc[8][4];
    #pragma unroll
    for (int n = 0; n < 8; n++)
        #pragma unroll
        for (int u = 0; u < 4; u++) oacc[n][u] = 0.f;

    for (int jt = 0; jt < T_/64; jt++) {
        const int j0 = jt * 64;
        __syncthreads();   // prev iter's PV done with Vs/Ps; safe to overwrite
        #pragma unroll
        for (int u = 0; u < 8; u++) {
            const int idx = u*128 + tid;
            const int r = idx >> 4, d4 = idx & 15;
            *(float4*)&Ks[r*68 + d4*4] = cvt4(*(const float4*)&kp[(size_t)(j0 + r)*D_ + d4*4]);
            *(float4*)&Vs[r*72 + d4*4] = cvt4(*(const float4*)&vp[(size_t)(j0 + r)*D_ + d4*4]);
        }
        #pragma unroll
        for (int u = 0; u < 4; u++) {      // bias: 64 rows x 8 uint4
            const int idx = u*128 + tid;
            const int br = idx >> 3, seg = idx & 7;
            *(uint4*)&Bb[(br >> 4)*2176 + (br & 15)*72 + seg*8] =
                *(const uint4*)&bp[(size_t)(i0 + br)*T_ + j0 + seg*8];
        }
        __syncthreads();

        // S = Q K^T
        float sacc[8][4];
        #pragma unroll
        for (int n = 0; n < 8; n++)
            #pragma unroll
            for (int u = 0; u < 4; u++) sacc[n][u] = 0.f;
        #pragma unroll
        for (int kk = 0; kk < 8; kk++) {
            const int kb = kk * 8;
            const int mr = slab + g;
            float afr[4];
            afr[0] = Qs[ mr     *68 + ((kb + qd    ) ^ sw)];
            afr[1] = Qs[(mr + 8)*68 + ((kb + qd    ) ^ sw)];
            afr[2] = Qs[ mr     *68 + ((kb + qd + 4) ^ sw)];
            afr[3] = Qs[(mr + 8)*68 + ((kb + qd + 4) ^ sw)];
            #pragma unroll
            for (int n = 0; n < 8; n++) {
                const int nr = n*8 + g;
                float bfr[2];
                bfr[0] = Ks[nr*68 + kb + qd];
                bfr[1] = Ks[nr*68 + kb + qd + 4];
                mma8(sacc[n], afr, bfr);
            }
        }

        // epilogue: s2 = sacc*SC2 + bias2 (log2 domain), online softmax
        // bias frag rows are warp-private (this warp's slab)
        float sv[8][4];
        float mx0 = -1e30f, mx1 = -1e30f;
        #pragma unroll
        for (int n = 0; n < 8; n++) {
            const int c = n*8 + qd*2;
            const float2 bv0 = __bfloat1622float2(*(const __nv_bfloat162*)&Bb[warp*2176 + g    *72 + c]);
            const float2 bv1 = __bfloat1622float2(*(const __nv_bfloat162*)&Bb[warp*2176 + (g+8)*72 + c]);
            sv[n][0] = fmaf(sacc[n][0], SC2_, bv0.x);
            sv[n][1] = fmaf(sacc[n][1], SC2_, bv0.y);
            sv[n][2] = fmaf(sacc[n][2], SC2_, bv1.x);
            sv[n][3] = fmaf(sacc[n][3], SC2_, bv1.y);
            mx0 = fmaxf(mx0, fmaxf(sv[n][0], sv[n][1]));
            mx1 = fmaxf(mx1, fmaxf(sv[n][2], sv[n][3]));
        }
        mx0 = fmaxf(mx0, __shfl_xor_sync(0xffffffffu, mx0, 1));
        mx0 = fmaxf(mx0, __shfl_xor_sync(0xffffffffu, mx0, 2));
        mx1 = fmaxf(mx1, __shfl_xor_sync(0xffffffffu, mx1, 1));
        mx1 = fmaxf(mx1, __shfl_xor_sync(0xffffffffu, mx1, 2));

        __syncwarp();      // all bias-frag reads in this warp done before P writes

        const float mn0 = fmaxf(m0, mx0), mn1 = fmaxf(m1, mx1);
        const float al0 = ex2(m0 - mn0),  al1 = ex2(m1 - mn1);
        float rs0 = 0.f, rs1 = 0.f;
        #pragma unroll
        for (int n = 0; n < 8; n++) {
            const float p0 = ex2(sv[n][0] - mn0);
            const float p1 = ex2(sv[n][1] - mn0);
            const float p2 = ex2(sv[n][2] - mn1);
            const float p3 = ex2(sv[n][3] - mn1);
            rs0 += p0 + p1; rs1 += p2 + p3;
            const int c = (n*8 + qd*2) ^ sw;
            *(float2*)&Pw[ g    *68 + c] = make_float2(to_tf32(p0), to_tf32(p1));
            *(float2*)&Pw[(g+8)*68 + c] = make_float2(to_tf32(p2), to_tf32(p3));
            oacc[n][0] *= al0; oacc[n][1] *= al0;
            oacc[n][2] *= al1; oacc[n][3] *= al1;
        }
        rs0 += __shfl_xor_sync(0xffffffffu, rs0, 1);
        rs0 += __shfl_xor_sync(0xffffffffu, rs0, 2);
        rs1 += __shfl_xor_sync(0xffffffffu, rs1, 1);
        rs1 += __shfl_xor_sync(0xffffffffu, rs1, 2);
        l0 = l0*al0 + rs0;  m0 = mn0;
        l1 = l1*al1 + rs1;  m1 = mn1;

        __syncwarp();      // P rows warp-private; intra-warp visibility only

        // O += P @ V
        #pragma unroll
        for (int kk = 0; kk < 8; kk++) {
            const int kb = kk * 8;
            float afr[4];
            afr[0] = Pw[ g    *68 + ((kb + qd    ) ^ sw)];
            afr[1] = Pw[(g+8)*68 + ((kb + qd    ) ^ sw)];
            afr[2] = Pw[ g    *68 + ((kb + qd + 4) ^ sw)];
            afr[3] = Pw[(g+8)*68 + ((kb + qd + 4) ^ sw)];
            #pragma unroll
            for (int n = 0; n < 8; n++) {
                float bfr[2];
                bfr[0] = Vs[(kb + qd    )*72 + n*8 + g];
                bfr[1] = Vs[(kb + qd + 4)*72 + n*8 + g];
                mma8(oacc[n], afr, bfr);
            }
        }
    }

    const float inv0 = 1.0f / l0, inv1 = 1.0f / l1;
    const size_t r0 = (size_t)b*T_ + i0 + slab + g;
    #pragma unroll
    for (int n = 0; n < 8; n++) {
        const int c = h*HD_ + n*8 + qd*2;
        *(float2*)&o[ r0      * D_ + c] = make_float2(oacc[n][0]*inv0, oacc[n][1]*inv0);
        *(float2*)&o[(r0 + 8) * D_ + c] = make_float2(oacc[n][2]*inv1, oacc[n][3]*inv1);
    }
}

// ---------------- embedding extras ------------------------------------------
__global__ void add_cent_kernel(float* __restrict__ h, const float* __restrict__ cent,
                                const float* __restrict__ cw, const float* __restrict__ cb)
{
    const int n = blockIdx.x, d = threadIdx.x;
    h[(size_t)n * D_ + d] += cent[n] * cw[d] + cb[d];
}

// biash[b,h,i,j] = (edge_emb[et,h] + dist_emb[sp,h]) * log2(e)  as bf16
__global__ void bias_kernel(const int* __restrict__ et, const int* __restrict__ sp,
                            const float* __restrict__ ee, const float* __restrict__ de,
                            __nv_bfloat16* __restrict__ bias)
{
    const size_t tid = (size_t)blockIdx.x * blockDim.x + threadIdx.x;  // B*T*T
    const int e = et[tid];
    int s = sp[tid]; if (s > MD_) s = MD_; if (s < 0) s = 0;
    const size_t j = tid & (T_ - 1);
    const size_t i = (tid >> 10) & (T_ - 1);
    const size_t b = tid >> 20;
    #pragma unroll
    for (int hh = 0; hh < H_; hh++)
        bias[(((b*H_ + hh)*T_ + i)*T_) + j] =
            __float2bfloat16((ee[e*H_ + hh] + de[s*H_ + hh]) * LOG2E_);
}

// ---------------- layernorm --------------------------------------------------
__global__ __launch_bounds__(128)
void ln_kernel(const float* __restrict__ h, const float* __restrict__ w,
               const float* __restrict__ b, float* __restrict__ out)
{
    __shared__ float red[8];
    const int t = threadIdx.x;
    const float* hp = h + (size_t)blockIdx.x * D_;
    float v[4]; float s = 0.f, s2 = 0.f;
    #pragma unroll
    for (int u = 0; u < 4; u++) { v[u] = hp[t + u*128]; s += v[u]; s2 += v[u]*v[u]; }
    s  = warp_red_sum(s);
    s2 = warp_red_sum(s2);
    if ((t & 31) == 0) { red[t>>5] = s; red[4 + (t>>5)] = s2; }
    __syncthreads();
    s  = red[0] + red[1] + red[2] + red[3];
    s2 = red[4] + red[5] + red[6] + red[7];
    const float m   = s  * (1.0f / D_);
    const float var = s2 * (1.0f / D_) - m * m;
    const float r   = rsqrtf(var + 1e-5f);
    float* op = out + (size_t)blockIdx.x * D_;
    #pragma unroll
    for (int u = 0; u < 4; u++) {
        const int d = t + u*128;
        op[d] = (v[u] - m) * r * w[d] + b[d];
    }
}

// ---------------- host-side orchestration -----------------------------------
static inline void gemm1(const float* A, const float* W, const float* bias,
                         const float* resid, float* C, int K, int N, int act)
{
    GemmP p;
    p.A = A;
    p.W[0] = p.W[1] = p.W[2] = W;
    p.bias[0] = p.bias[1] = p.bias[2] = bias;
    p.C[0] = p.C[1] = p.C[2] = C;
    p.resid = resid;
    p.K = K; p.N = N;
    dim3 g(N / 128, NT_ / 128, 1);
    if (act == 1)        gemm_tf32<1,false><<<g,256>>>(p);
    else if (resid)      gemm_tf32<0,true ><<<g,256>>>(p);
    else                 gemm_tf32<0,false><<<g,256>>>(p);
}

extern "C" void kernel_launch(void* const* d_in, const int* in_sizes, int n_in,
                              void* d_out, int out_size)
{
    const float* nf     = (const float*)d_in[0];
    const float* cent   = (const float*)d_in[1];
    const int*   et     = (const int*)  d_in[2];
    const int*   sp     = (const int*)  d_in[3];
    const float* node_W = (const float*)d_in[4];
    const float* node_b = (const float*)d_in[5];
    const float* cent_W = (const float*)d_in[6];
    const float* cent_b = (const float*)d_in[7];
    const float* e_emb  = (const float*)d_in[8];
    const float* d_emb  = (const float*)d_in[9];
    const float* ln1w   = (const float*)d_in[10];
    const float* ln1b   = (const float*)d_in[11];
    const float* qW     = (const float*)d_in[12];
    const float* qb     = (const float*)d_in[13];
    const float* kW     = (const float*)d_in[14];
    const float* kb     = (const float*)d_in[15];
    const float* vW     = (const float*)d_in[16];
    const float* vb     = (const float*)d_in[17];
    const float* oW     = (const float*)d_in[18];
    const float* ob     = (const float*)d_in[19];
    const float* ln2w   = (const float*)d_in[20];
    const float* ln2b   = (const float*)d_in[21];
    const float* f1W    = (const float*)d_in[22];
    const float* f1b    = (const float*)d_in[23];
    const float* f2W    = (const float*)d_in[24];
    const float* f2b    = (const float*)d_in[25];

    float* h = (float*)d_out;

    float *px, *pq, *pk, *pv, *po, *pffn;
    __nv_bfloat16* pbias;
    cudaGetSymbolAddress((void**)&px,    g_x);
    cudaGetSymbolAddress((void**)&pq,    g_q);
    cudaGetSymbolAddress((void**)&pk,    g_k);
    cudaGetSymbolAddress((void**)&pv,    g_v);
    cudaGetSymbolAddress((void**)&po,    g_o);
    cudaGetSymbolAddress((void**)&pffn,  g_ffn);
    cudaGetSymbolAddress((void**)&pbias, g_biash);

    cudaFuncSetAttribute(flash_tf32, cudaFuncAttributeMaxDynamicSharedMemorySize, FL_SMEM);

    // embedding: h = nf @ node_W + node_b ; h += cent*cent_W + cent_b
    gemm1(nf, node_W, node_b, nullptr, h, F_, D_, 0);
    add_cent_kernel<<<NT_, D_>>>(h, cent, cent_W, cent_b);

    // Graphormer attention bias (layer-invariant), bf16, log2e pre-folded
    bias_kernel<<<(B_*T_*T_)/256, 256>>>(et, sp, e_emb, d_emb, pbias);

    for (int l = 0; l < L_; l++) {
        const size_t wd = (size_t)l * D_ * D_;
        // x = LN1(h)
        ln_kernel<<<NT_, 128>>>(h, ln1w + l*D_, ln1b + l*D_, px);
        // q,k,v in one batched launch (grid.z = 3)
        {
            GemmP p;
            p.A = px;
            p.W[0] = qW + wd;  p.W[1] = kW + wd;  p.W[2] = vW + wd;
            p.bias[0] = qb + l*D_; p.bias[1] = kb + l*D_; p.bias[2] = vb + l*D_;
            p.C[0] = pq; p.C[1] = pk; p.C[2] = pv;
            p.resid = nullptr;
            p.K = D_; p.N = D_;
            gemm_tf32<0,false><<<dim3(D_/128, NT_/128, 3), 256>>>(p);
        }
        // fused attention: scores + softmax + AV, no global scores
        flash_tf32<<<dim3(T_/64, B_*H_), 128, FL_SMEM>>>(pq, pk, pv, pbias, po);
        // h += o @ oW + ob
        gemm1(po, oW + wd, ob + l*D_, h, h, D_, D_, 0);
        // FFN
        ln_kernel<<<NT_, 128>>>(h, ln2w + l*D_, ln2b + l*D_, px);
        gemm1(px,   f1W + (size_t)l*D_*DFF_, f1b + l*DFF_, nullptr, pffn, D_,   DFF_, 1);
        gemm1(pffn, f2W + (size_t)l*DFF_*D_, f2b + l*D_,   h,       h,    DFF_, D_,   0);
    }
}

// round 7
// speedup vs baseline: 1.5809x; 1.0694x over previous
#include <cuda_runtime.h>
#include <cuda_bf16.h>
#include <math.h>
#include <stdint.h>

#define B_ 4
#define T_ 1024
#define F_ 128
#define D_ 512
#define H_ 8
#define L_ 4
#define DFF_ 2048
#define MD_ 20
#define HD_ 64
#define NT_ (B_*T_)
#define SCALE_ 0.125f
#define LOG2E_ 1.4426950408889634f
#define SC2_ (SCALE_*LOG2E_)

// ---------------- scratch (device globals: no allocations allowed) ----------
__device__ float g_x  [NT_*(size_t)D_];
__device__ float g_q  [NT_*(size_t)D_];
__device__ float g_k  [NT_*(size_t)D_];
__device__ float g_v  [NT_*(size_t)D_];
__device__ float g_o  [NT_*(size_t)D_];
__device__ float g_ffn[NT_*(size_t)DFF_];
__device__ __nv_bfloat16 g_biash[(size_t)B_*H_*T_*T_];   // bias * log2(e), bf16

// ---------------- tf32 helpers ----------------------------------------------
__device__ __forceinline__ float to_tf32(float x) {
    float y; asm("cvt.rna.tf32.f32 %0, %1;" : "=f"(y) : "f"(x)); return y;
}
__device__ __forceinline__ float4 cvt4(float4 v) {
    v.x = to_tf32(v.x); v.y = to_tf32(v.y); v.z = to_tf32(v.z); v.w = to_tf32(v.w);
    return v;
}
__device__ __forceinline__ float ex2(float x) {
    float y; asm("ex2.approx.f32 %0, %1;" : "=f"(y) : "f"(x)); return y;
}
// D += A(16x8,row) * B(8x8,col);  A,B hold tf32 bit patterns in fp32 regs.
__device__ __forceinline__ void mma8(float* d, const float* a, const float* b) {
    asm volatile(
      "mma.sync.aligned.m16n8k8.row.col.f32.tf32.tf32.f32 "
      "{%0,%1,%2,%3}, {%4,%5,%6,%7}, {%8,%9}, {%0,%1,%2,%3};\n"
      : "+f"(d[0]), "+f"(d[1]), "+f"(d[2]), "+f"(d[3])
      : "r"(__float_as_uint(a[0])), "r"(__float_as_uint(a[1])),
        "r"(__float_as_uint(a[2])), "r"(__float_as_uint(a[3])),
        "r"(__float_as_uint(b[0])), "r"(__float_as_uint(b[1])));
}

__device__ __forceinline__ float warp_red_sum(float v) {
    #pragma unroll
    for (int o = 16; o > 0; o >>= 1) v += __shfl_xor_sync(0xffffffffu, v, o);
    return v;
}

// ---------------- tf32 GEMM: C[M=4096, N] = act(A[M,K] @ W[K,N] + bias) -----
// 128x128x32 block tile, 256 threads, warp tile 64x32 (m16n8k8 frags).
// TWO-STAGE smem double buffer: one __syncthreads per K-chunk; LDG of chunk
// kt+2 issued while mma of chunk kt runs -> global latency fully hidden.
#define AS_ELEMS (128*36)
#define BS_ELEMS (32*136)
#define GEMM_SMEM ((2*(AS_ELEMS + BS_ELEMS))*4)   // 71680 B

struct GemmP {
    const float* A;
    const float* W[3];
    const float* bias[3];
    float*       C[3];
    const float* resid;
    int K, N;
};

template<int ACT, bool RESID>
__global__ __launch_bounds__(256)
void gemm_tf32(GemmP p)
{
    extern __shared__ float sm[];
    float* Asb = sm;                       // [2][128*36]
    float* Bsb = sm + 2*AS_ELEMS;          // [2][32*136]

    const int z = blockIdx.z;
    const float* __restrict__ A    = p.A;
    const float* __restrict__ W    = p.W[z];
    const float* __restrict__ bias = p.bias[z];
    float*       __restrict__ C    = p.C[z];
    const float* __restrict__ resid = p.resid;
    const int K = p.K, N = p.N;
    const int m0 = blockIdx.y * 128, n0 = blockIdx.x * 128;

    const int tid  = threadIdx.x;
    const int warp = tid >> 5, lane = tid & 31;
    const int g  = lane >> 2, qd = lane & 3;
    const int wm = (warp >> 2) * 64;
    const int wn = (warp & 3)  * 32;

    const int a_m  = tid >> 3;
    const int a_k4 = tid & 7;
    const int b_k  = tid >> 5;
    const int b_n4 = tid & 31;

    float4 ra[4], rb[4];
    float acc[4][4][4];
    #pragma unroll
    for (int i = 0; i < 4; i++)
        #pragma unroll
        for (int j = 0; j < 4; j++)
            #pragma unroll
            for (int u = 0; u < 4; u++) acc[i][j][u] = 0.f;

    const int nk = K >> 5;

    // prologue: chunk 0 -> regs -> smem buf 0
    #pragma unroll
    for (int i = 0; i < 4; i++)
        ra[i] = *(const float4*)&A[(size_t)(m0 + a_m + 32*i) * K + a_k4*4];
    #pragma unroll
    for (int i = 0; i < 4; i++)
        rb[i] = *(const float4*)&W[(size_t)(b_k + 8*i) * N + n0 + b_n4*4];
    #pragma unroll
    for (int i = 0; i < 4; i++) {
        const int m = a_m + 32*i;
        *(float4*)&Asb[m*36 + ((a_k4*4) ^ ((m & 3) << 3))] = cvt4(ra[i]);
    }
    #pragma unroll
    for (int i = 0; i < 4; i++)
        *(float4*)&Bsb[(b_k + 8*i)*136 + b_n4*4] = cvt4(rb[i]);
    __syncthreads();

    // chunk 1 -> regs (in flight during first mma block)
    if (nk > 1) {
        #pragma unroll
        for (int i = 0; i < 4; i++)
            ra[i] = *(const float4*)&A[(size_t)(m0 + a_m + 32*i) * K + 32 + a_k4*4];
        #pragma unroll
        for (int i = 0; i < 4; i++)
            rb[i] = *(const float4*)&W[(size_t)(32 + b_k + 8*i) * N + n0 + b_n4*4];
    }

    for (int kt = 0; kt < nk; kt++) {
        const float* As = Asb + (kt & 1) * AS_ELEMS;
        const float* Bs = Bsb + (kt & 1) * BS_ELEMS;

        #pragma unroll
        for (int kk = 0; kk < 4; kk++) {
            const int kb = kk * 8;
            float afr[4][4], bfr[4][2];
            #pragma unroll
            for (int mi = 0; mi < 4; mi++) {
                const int m_ = wm + mi*16 + g;
                const int sw = (m_ & 3) << 3;
                afr[mi][0] = As[ m_     *36 + ((kb + qd    ) ^ sw)];
                afr[mi][1] = As[(m_ + 8)*36 + ((kb + qd    ) ^ sw)];
                afr[mi][2] = As[ m_     *36 + ((kb + qd + 4) ^ sw)];
                afr[mi][3] = As[(m_ + 8)*36 + ((kb + qd + 4) ^ sw)];
            }
            #pragma unroll
            for (int ni = 0; ni < 4; ni++) {
                const int n_ = wn + ni*8 + g;
                bfr[ni][0] = Bs[(kb + qd    )*136 + n_];
                bfr[ni][1] = Bs[(kb + qd + 4)*136 + n_];
            }
            #pragma unroll
            for (int mi = 0; mi < 4; mi++)
                #pragma unroll
                for (int ni = 0; ni < 4; ni++)
                    mma8(acc[mi][ni], afr[mi], bfr[ni]);
        }

        if (kt + 1 < nk) {
            // stage chunk kt+1 (already in regs) into the other buffer
            float* Asw = Asb + ((kt + 1) & 1) * AS_ELEMS;
            float* Bsw = Bsb + ((kt + 1) & 1) * BS_ELEMS;
            #pragma unroll
            for (int i = 0; i < 4; i++) {
                const int m = a_m + 32*i;
                *(float4*)&Asw[m*36 + ((a_k4*4) ^ ((m & 3) << 3))] = cvt4(ra[i]);
            }
            #pragma unroll
            for (int i = 0; i < 4; i++)
                *(float4*)&Bsw[(b_k + 8*i)*136 + b_n4*4] = cvt4(rb[i]);
            // issue LDG for chunk kt+2
            if (kt + 2 < nk) {
                const int k0 = (kt + 2) << 5;
                #pragma unroll
                for (int i = 0; i < 4; i++)
                    ra[i] = *(const float4*)&A[(size_t)(m0 + a_m + 32*i) * K + k0 + a_k4*4];
                #pragma unroll
                for (int i = 0; i < 4; i++)
                    rb[i] = *(const float4*)&W[(size_t)(k0 + b_k + 8*i) * N + n0 + b_n4*4];
            }
            __syncthreads();
        }
    }

    // epilogue
    #pragma unroll
    for (int mi = 0; mi < 4; mi++) {
        const int r0 = m0 + wm + mi*16 + g;
        #pragma unroll
        for (int ni = 0; ni < 4; ni++) {
            const int c0 = n0 + wn + ni*8 + qd*2;
            const float2 bv = *(const float2*)&bias[c0];
            float v0 = acc[mi][ni][0] + bv.x;
            float v1 = acc[mi][ni][1] + bv.y;
            float v2 = acc[mi][ni][2] + bv.x;
            float v3 = acc[mi][ni][3] + bv.y;
            if (ACT == 1) {
                v0 = v0 / (1.0f + __expf(-v0));
                v1 = v1 / (1.0f + __expf(-v1));
                v2 = v2 / (1.0f + __expf(-v2));
                v3 = v3 / (1.0f + __expf(-v3));
            }
            if (RESID) {
                const float2 r1 = *(const float2*)&resid[(size_t)r0 * N + c0];
                const float2 r2 = *(const float2*)&resid[(size_t)(r0 + 8) * N + c0];
                v0 += r1.x; v1 += r1.y; v2 += r2.x; v3 += r2.y;
            }
            *(float2*)&C[(size_t)r0       * N + c0] = make_float2(v0, v1);
            *(float2*)&C[(size_t)(r0 + 8) * N + c0] = make_float2(v2, v3);
        }
    }
}

// ---------------- fused flash attention v2 (tf32) ---------------------------
// Grid (T/64, B*H), 128 threads = 4 warps; warp owns 16 q-rows x full 64-col
// j tile -> warp-local online softmax. Q frags live in REGISTERS (staged once
// through the P buffer) -> smem 53KB -> 4 CTAs/SM -> grid 512 fits one wave.
#define FL_SMEM (53248)

__global__ __launch_bounds__(128, 4)
void flash_tf32(const float* __restrict__ q, const float* __restrict__ k,
                const float* __restrict__ v,
                const __nv_bfloat16* __restrict__ biash,
                float* __restrict__ o)
{
    extern __shared__ char smem_raw[];
    float* Ks = (float*)smem_raw;                 // [64][68]
    float* Vs = Ks + 64*68;                       // [64][72]
    float* Ps = Vs + 64*72;                       // [64][68] swizzled (union w/ bias)
    __nv_bfloat16* Bb = (__nv_bfloat16*)Ps;       // bias: warp w rows at w*2176 + (r&15)*72

    const int z = blockIdx.y;
    const int b = z >> 3, h = z & 7;
    const int i0 = blockIdx.x * 64;
    const float* qp = q + (size_t)b*T_*D_ + h*HD_;
    const float* kp = k + (size_t)b*T_*D_ + h*HD_;
    const float* vp = v + (size_t)b*T_*D_ + h*HD_;
    const __nv_bfloat16* bp = biash + (size_t)z*T_*T_;

    const int tid = threadIdx.x;
    const int warp = tid >> 5, lane = tid & 31;
    const int g = lane >> 2, qd = lane & 3;
    const int slab = warp * 16;
    const int sw = (g & 3) << 3;          // swizzle for rows slab+g, slab+g+8
    float* Pw = Ps + warp * 1088;         // this warp's P slab [16][68]

    // stage Q through Ps once, lift this warp's frags into registers
    #pragma unroll
    for (int u = 0; u < 8; u++) {
        const int idx = u*128 + tid;
        const int r = idx >> 4, d4 = idx & 15;
        float4 val = cvt4(*(const float4*)&qp[(size_t)(i0 + r)*D_ + d4*4]);
        *(float4*)&Ps[r*68 + ((d4*4) ^ ((r & 3) << 3))] = val;
    }
    __syncthreads();
    float qf[8][4];
    #pragma unroll
    for (int kk = 0; kk < 8; kk++) {
        const int kb = kk * 8;
        const int mr = slab + g;
        qf[kk][0] = Ps[ mr     *68 + ((kb + qd    ) ^ sw)];
        qf[kk][1] = Ps[(mr + 8)*68 + ((kb + qd    ) ^ sw)];
        qf[kk][2] = Ps[ mr     *68 + ((kb + qd + 4) ^ sw)];
        qf[kk][3] = Ps[(mr + 8)*68 + ((kb + qd + 4) ^ sw)];
    }
    // first loop iteration begins with __syncthreads -> safe to reuse Ps

    float m0 = -1e30f, m1 = -1e30f, l0 = 0.f, l1 = 0.f;
    float oacc[8][4];
    #pragma unroll
    for (int n = 0; n < 8; n++)
        #pragma unroll
        for (int u = 0; u < 4; u++) oacc[n][u] = 0.f;

    for (int jt = 0; jt < T_/64; jt++) {
        const int j0 = jt * 64;
        __syncthreads();   // prev iter's PV done with Vs/Ps; safe to overwrite
        #pragma unroll
        for (int u = 0; u < 8; u++) {
            const int idx = u*128 + tid;
            const int r = idx >> 4, d4 = idx & 15;
            *(float4*)&Ks[r*68 + d4*4] = cvt4(*(const float4*)&kp[(size_t)(j0 + r)*D_ + d4*4]);
            *(float4*)&Vs[r*72 + d4*4] = cvt4(*(const float4*)&vp[(size_t)(j0 + r)*D_ + d4*4]);
        }
        #pragma unroll
        for (int u = 0; u < 4; u++) {      // bias: 64 rows x 8 uint4
            const int idx = u*128 + tid;
            const int br = idx >> 3, seg = idx & 7;
            *(uint4*)&Bb[(br >> 4)*2176 + (br & 15)*72 + seg*8] =
                *(const uint4*)&bp[(size_t)(i0 + br)*T_ + j0 + seg*8];
        }
        __syncthreads();

        // S = Q K^T (Q frags from registers)
        float sacc[8][4];
        #pragma unroll
        for (int n = 0; n < 8; n++)
            #pragma unroll
            for (int u = 0; u < 4; u++) sacc[n][u] = 0.f;
        #pragma unroll
        for (int kk = 0; kk < 8; kk++) {
            const int kb = kk * 8;
            #pragma unroll
            for (int n = 0; n < 8; n++) {
                const int nr = n*8 + g;
                float bfr[2];
                bfr[0] = Ks[nr*68 + kb + qd];
                bfr[1] = Ks[nr*68 + kb + qd + 4];
                mma8(sacc[n], qf[kk], bfr);
            }
        }

        // epilogue: s2 = sacc*SC2 + bias2 (log2 domain), online softmax
        float sv[8][4];
        float mx0 = -1e30f, mx1 = -1e30f;
        #pragma unroll
        for (int n = 0; n < 8; n++) {
            const int c = n*8 + qd*2;
            const float2 bv0 = __bfloat1622float2(*(const __nv_bfloat162*)&Bb[warp*2176 + g    *72 + c]);
            const float2 bv1 = __bfloat1622float2(*(const __nv_bfloat162*)&Bb[warp*2176 + (g+8)*72 + c]);
            sv[n][0] = fmaf(sacc[n][0], SC2_, bv0.x);
            sv[n][1] = fmaf(sacc[n][1], SC2_, bv0.y);
            sv[n][2] = fmaf(sacc[n][2], SC2_, bv1.x);
            sv[n][3] = fmaf(sacc[n][3], SC2_, bv1.y);
            mx0 = fmaxf(mx0, fmaxf(sv[n][0], sv[n][1]));
            mx1 = fmaxf(mx1, fmaxf(sv[n][2], sv[n][3]));
        }
        mx0 = fmaxf(mx0, __shfl_xor_sync(0xffffffffu, mx0, 1));
        mx0 = fmaxf(mx0, __shfl_xor_sync(0xffffffffu, mx0, 2));
        mx1 = fmaxf(mx1, __shfl_xor_sync(0xffffffffu, mx1, 1));
        mx1 = fmaxf(mx1, __shfl_xor_sync(0xffffffffu, mx1, 2));

        __syncwarp();      // all bias-frag reads in this warp done before P writes

        const float mn0 = fmaxf(m0, mx0), mn1 = fmaxf(m1, mx1);
        const float al0 = ex2(m0 - mn0),  al1 = ex2(m1 - mn1);
        float rs0 = 0.f, rs1 = 0.f;
        #pragma unroll
        for (int n = 0; n < 8; n++) {
            const float p0 = ex2(sv[n][0] - mn0);
            const float p1 = ex2(sv[n][1] - mn0);
            const float p2 = ex2(sv[n][2] - mn1);
            const float p3 = ex2(sv[n][3] - mn1);
            rs0 += p0 + p1; rs1 += p2 + p3;
            const int c = (n*8 + qd*2) ^ sw;
            *(float2*)&Pw[ g    *68 + c] = make_float2(to_tf32(p0), to_tf32(p1));
            *(float2*)&Pw[(g+8)*68 + c] = make_float2(to_tf32(p2), to_tf32(p3));
            oacc[n][0] *= al0; oacc[n][1] *= al0;
            oacc[n][2] *= al1; oacc[n][3] *= al1;
        }
        rs0 += __shfl_xor_sync(0xffffffffu, rs0, 1);
        rs0 += __shfl_xor_sync(0xffffffffu, rs0, 2);
        rs1 += __shfl_xor_sync(0xffffffffu, rs1, 1);
        rs1 += __shfl_xor_sync(0xffffffffu, rs1, 2);
        l0 = l0*al0 + rs0;  m0 = mn0;
        l1 = l1*al1 + rs1;  m1 = mn1;

        __syncwarp();      // P rows warp-private; intra-warp visibility only

        // O += P @ V
        #pragma unroll
        for (int kk = 0; kk < 8; kk++) {
            const int kb = kk * 8;
            float afr[4];
            afr[0] = Pw[ g    *68 + ((kb + qd    ) ^ sw)];
            afr[1] = Pw[(g+8)*68 + ((kb + qd    ) ^ sw)];
            afr[2] = Pw[ g    *68 + ((kb + qd + 4) ^ sw)];
            afr[3] = Pw[(g+8)*68 + ((kb + qd + 4) ^ sw)];
            #pragma unroll
            for (int n = 0; n < 8; n++) {
                float bfr[2];
                bfr[0] = Vs[(kb + qd    )*72 + n*8 + g];
                bfr[1] = Vs[(kb + qd + 4)*72 + n*8 + g];
                mma8(oacc[n], afr, bfr);
            }
        }
    }

    const float inv0 = 1.0f / l0, inv1 = 1.0f / l1;
    const size_t r0 = (size_t)b*T_ + i0 + slab + g;
    #pragma unroll
    for (int n = 0; n < 8; n++) {
        const int c = h*HD_ + n*8 + qd*2;
        *(float2*)&o[ r0      * D_ + c] = make_float2(oacc[n][0]*inv0, oacc[n][1]*inv0);
        *(float2*)&o[(r0 + 8) * D_ + c] = make_float2(oacc[n][2]*inv1, oacc[n][3]*inv1);
    }
}

// ---------------- embedding extras ------------------------------------------
__global__ void add_cent_kernel(float* __restrict__ h, const float* __restrict__ cent,
                                const float* __restrict__ cw, const float* __restrict__ cb)
{
    const int n = blockIdx.x, d = threadIdx.x;
    h[(size_t)n * D_ + d] += cent[n] * cw[d] + cb[d];
}

// biash[b,h,i,j] = (edge_emb[et,h] + dist_emb[sp,h]) * log2(e)  as bf16
__global__ void bias_kernel(const int* __restrict__ et, const int* __restrict__ sp,
                            const float* __restrict__ ee, const float* __restrict__ de,
                            __nv_bfloat16* __restrict__ bias)
{
    const size_t tid = (size_t)blockIdx.x * blockDim.x + threadIdx.x;  // B*T*T
    const int e = et[tid];
    int s = sp[tid]; if (s > MD_) s = MD_; if (s < 0) s = 0;
    const size_t j = tid & (T_ - 1);
    const size_t i = (tid >> 10) & (T_ - 1);
    const size_t b = tid >> 20;
    #pragma unroll
    for (int hh = 0; hh < H_; hh++)
        bias[(((b*H_ + hh)*T_ + i)*T_) + j] =
            __float2bfloat16((ee[e*H_ + hh] + de[s*H_ + hh]) * LOG2E_);
}

// ---------------- layernorm --------------------------------------------------
__global__ __launch_bounds__(128)
void ln_kernel(const float* __restrict__ h, const float* __restrict__ w,
               const float* __restrict__ b, float* __restrict__ out)
{
    __shared__ float red[8];
    const int t = threadIdx.x;
    const float* hp = h + (size_t)blockIdx.x * D_;
    float v[4]; float s = 0.f, s2 = 0.f;
    #pragma unroll
    for (int u = 0; u < 4; u++) { v[u] = hp[t + u*128]; s += v[u]; s2 += v[u]*v[u]; }
    s  = warp_red_sum(s);
    s2 = warp_red_sum(s2);
    if ((t & 31) == 0) { red[t>>5] = s; red[4 + (t>>5)] = s2; }
    __syncthreads();
    s  = red[0] + red[1] + red[2] + red[3];
    s2 = red[4] + red[5] + red[6] + red[7];
    const float m   = s  * (1.0f / D_);
    const float var = s2 * (1.0f / D_) - m * m;
    const float r   = rsqrtf(var + 1e-5f);
    float* op = out + (size_t)blockIdx.x * D_;
    #pragma unroll
    for (int u = 0; u < 4; u++) {
        const int d = t + u*128;
        op[d] = (v[u] - m) * r * w[d] + b[d];
    }
}

// ---------------- host-side orchestration -----------------------------------
static inline void gemm1(const float* A, const float* W, const float* bias,
                         const float* resid, float* C, int K, int N, int act)
{
    GemmP p;
    p.A = A;
    p.W[0] = p.W[1] = p.W[2] = W;
    p.bias[0] = p.bias[1] = p.bias[2] = bias;
    p.C[0] = p.C[1] = p.C[2] = C;
    p.resid = resid;
    p.K = K; p.N = N;
    dim3 g(N / 128, NT_ / 128, 1);
    if (act == 1)        gemm_tf32<1,false><<<g,256,GEMM_SMEM>>>(p);
    else if (resid)      gemm_tf32<0,true ><<<g,256,GEMM_SMEM>>>(p);
    else                 gemm_tf32<0,false><<<g,256,GEMM_SMEM>>>(p);
}

extern "C" void kernel_launch(void* const* d_in, const int* in_sizes, int n_in,
                              void* d_out, int out_size)
{
    const float* nf     = (const float*)d_in[0];
    const float* cent   = (const float*)d_in[1];
    const int*   et     = (const int*)  d_in[2];
    const int*   sp     = (const int*)  d_in[3];
    const float* node_W = (const float*)d_in[4];
    const float* node_b = (const float*)d_in[5];
    const float* cent_W = (const float*)d_in[6];
    const float* cent_b = (const float*)d_in[7];
    const float* e_emb  = (const float*)d_in[8];
    const float* d_emb  = (const float*)d_in[9];
    const float* ln1w   = (const float*)d_in[10];
    const float* ln1b   = (const float*)d_in[11];
    const float* qW     = (const float*)d_in[12];
    const float* qb     = (const float*)d_in[13];
    const float* kW     = (const float*)d_in[14];
    const float* kb     = (const float*)d_in[15];
    const float* vW     = (const float*)d_in[16];
    const float* vb     = (const float*)d_in[17];
    const float* oW     = (const float*)d_in[18];
    const float* ob     = (const float*)d_in[19];
    const float* ln2w   = (const float*)d_in[20];
    const float* ln2b   = (const float*)d_in[21];
    const float* f1W    = (const float*)d_in[22];
    const float* f1b    = (const float*)d_in[23];
    const float* f2W    = (const float*)d_in[24];
    const float* f2b    = (const float*)d_in[25];

    float* h = (float*)d_out;

    float *px, *pq, *pk, *pv, *po, *pffn;
    __nv_bfloat16* pbias;
    cudaGetSymbolAddress((void**)&px,    g_x);
    cudaGetSymbolAddress((void**)&pq,    g_q);
    cudaGetSymbolAddress((void**)&pk,    g_k);
    cudaGetSymbolAddress((void**)&pv,    g_v);
    cudaGetSymbolAddress((void**)&po,    g_o);
    cudaGetSymbolAddress((void**)&pffn,  g_ffn);
    cudaGetSymbolAddress((void**)&pbias, g_biash);

    cudaFuncSetAttribute(flash_tf32, cudaFuncAttributeMaxDynamicSharedMemorySize, FL_SMEM);
    cudaFuncSetAttribute(gemm_tf32<0,false>, cudaFuncAttributeMaxDynamicSharedMemorySize, GEMM_SMEM);
    cudaFuncSetAttribute(gemm_tf32<0,true >, cudaFuncAttributeMaxDynamicSharedMemorySize, GEMM_SMEM);
    cudaFuncSetAttribute(gemm_tf32<1,false>, cudaFuncAttributeMaxDynamicSharedMemorySize, GEMM_SMEM);

    // embedding: h = nf @ node_W + node_b ; h += cent*cent_W + cent_b
    gemm1(nf, node_W, node_b, nullptr, h, F_, D_, 0);
    add_cent_kernel<<<NT_, D_>>>(h, cent, cent_W, cent_b);

    // Graphormer attention bias (layer-invariant), bf16, log2e pre-folded
    bias_kernel<<<(B_*T_*T_)/256, 256>>>(et, sp, e_emb, d_emb, pbias);

    for (int l = 0; l < L_; l++) {
        const size_t wd = (size_t)l * D_ * D_;
        // x = LN1(h)
        ln_kernel<<<NT_, 128>>>(h, ln1w + l*D_, ln1b + l*D_, px);
        // q,k,v in one batched launch (grid.z = 3)
        {
            GemmP p;
            p.A = px;
            p.W[0] = qW + wd;  p.W[1] = kW + wd;  p.W[2] = vW + wd;
            p.bias[0] = qb + l*D_; p.bias[1] = kb + l*D_; p.bias[2] = vb + l*D_;
            p.C[0] = pq; p.C[1] = pk; p.C[2] = pv;
            p.resid = nullptr;
            p.K = D_; p.N = D_;
            gemm_tf32<0,false><<<dim3(D_/128, NT_/128, 3), 256, GEMM_SMEM>>>(p);
        }
        // fused attention: scores + softmax + AV, no global scores
        flash_tf32<<<dim3(T_/64, B_*H_), 128, FL_SMEM>>>(pq, pk, pv, pbias, po);
        // h += o @ oW + ob
        gemm1(po, oW + wd, ob + l*D_, h, h, D_, D_, 0);
        // FFN
        ln_kernel<<<NT_, 128>>>(h, ln2w + l*D_, ln2b + l*D_, px);
        gemm1(px,   f1W + (size_t)l*D_*DFF_, f1b + l*DFF_, nullptr, pffn, D_,   DFF_, 1);
        gemm1(pffn, f2W + (size_t)l*DFF_*D_, f2b + l*D_,   h,       h,    DFF_, D_,   0);
    }
}